// round 8
// baseline (speedup 1.0000x reference)
#include <cuda_runtime.h>
#include <cuda_fp16.h>
#include <math.h>

#define T_LEN   2048
#define TMASK   2047
#define NKEEP   1536
#define EDGE    256
#define NBC     16
#define NBAND   80
#define PHA_NB  50
#define AMP_NB  30
#define NBINS   18
#define NKTOT   640
#define NEV     160
#define KCH     80
#define NCH     8
#define AMP_STR 32          // padded amp row (halves); col30=count, col31=0
#define TS2     8
#define TPB2    (NKEEP / TS2)   // 192 t per mi block
#define NTB     (NKEEP / 128)   // 12 t-blocks in prefix

// ---------------- f32x2 packed helpers (sm_103a) -----------------------------
typedef unsigned long long u64;
__device__ __forceinline__ u64 pk2(float lo, float hi) {
    u64 d; asm("mov.b64 %0,{%1,%2};" : "=l"(d) : "f"(lo), "f"(hi)); return d;
}
__device__ __forceinline__ void up2(u64 v, float& lo, float& hi) {
    asm("mov.b64 {%0,%1},%2;" : "=f"(lo), "=f"(hi) : "l"(v));
}
__device__ __forceinline__ u64 fma2(u64 a, u64 b, u64 c) {
    u64 d; asm("fma.rn.f32x2 %0,%1,%2,%3;" : "=l"(d) : "l"(a), "l"(b), "l"(c)); return d;
}
__device__ __forceinline__ u64 add2(u64 a, u64 b) {
    u64 d; asm("add.rn.f32x2 %0,%1,%2;" : "=l"(d) : "l"(a), "l"(b)); return d;
}
__device__ __forceinline__ u64 mul2(u64 a, u64 b) {
    u64 d; asm("mul.rn.f32x2 %0,%1,%2;" : "=l"(d) : "l"(a), "l"(b)); return d;
}

// ---------------- compile-time tables ---------------------------------------
struct Tables {
    int evk[NEV];
    int evslot[NEV];
    int evstart[NCH + 1];
    int cha[NBAND];
    int chb[NBAND];
};

constexpr Tables make_tables() {
    Tables tb{};
    int klo[NBAND] = {}, khi[NBAND] = {};
    for (int b = 0; b < NBAND; b++) {
        double lo_d = 0.0, hi_d = 0.0;
        if (b < PHA_NB) {
            double step = 18.0 / 49.0;
            double mid  = (b == PHA_NB - 1) ? 20.0 : ((double)b * step + 2.0);
            lo_d = mid * 0.75; hi_d = mid * 1.25;
        } else {
            int i = b - PHA_NB;
            double step = (141.0 - 60.0) / 29.0;
            double mid  = (i == AMP_NB - 1) ? 141.0 : ((double)i * step + 60.0);
            lo_d = mid * 0.875; hi_d = mid * 1.125;
        }
        float lo = (float)lo_d, hi = (float)hi_d;
        int kl = -1, kh = -2;
        for (int k = 1; k < NKTOT; k++) {
            float f = (float)k * 0.25f;
            if (f >= lo && f <= hi) { if (kl < 0) kl = k; kh = k; }
        }
        klo[b] = kl; khi[b] = kh;
        tb.cha[b] = (kl - 1) / KCH;
        tb.chb[b] = kh / KCH;
    }
    int key[NEV] = {}, slot[NEV] = {};
    for (int e = 0; e < NEV; e++) {
        int b = e >> 1, type = e & 1;
        key[e]  = type ? khi[b] : (klo[b] - 1);
        slot[e] = e;
    }
    for (int i = 1; i < NEV; i++) {
        int k2 = key[i], s2 = slot[i], j = i - 1;
        while (j >= 0 && key[j] > k2) { key[j+1] = key[j]; slot[j+1] = slot[j]; j--; }
        key[j+1] = k2; slot[j+1] = s2;
    }
    for (int e = 0; e < NEV; e++) { tb.evk[e] = key[e]; tb.evslot[e] = slot[e]; }
    for (int c = 0; c <= NCH; c++) {
        int s = 0;
        while (s < NEV && key[s] < c * KCH) s++;
        tb.evstart[c] = s;
    }
    return tb;
}
__constant__ Tables c_tab = make_tables();

// ---------------- scratch -----------------------------------------------------
__device__ float2        g_Xf[NBC][NKTOT];
__device__ float2        g_pref[NBC][NEV][NKEEP];
__device__ float2        g_ctot[NCH - 1][NBC][NKEEP];
__device__ unsigned char g_pidx[NBC][PHA_NB][NKEEP];
__device__ __half        g_amp[NBC][NKEEP][AMP_STR];
__device__ float2        g_part[NBC][PHA_NB][TS2][NBINS][16];
__device__ int           g_cnt[NBC][PHA_NB / 2];     // mi fusion counters
__device__ int           g_tcnt[NBC][NTB];           // tail fusion counters

// ---------------- kernel 1: fused 2-stage DFT (t = 32a + b) -----------------
__global__ __launch_bounds__(1024) void dft_kernel(const float* __restrict__ x) {
    __shared__ float  s_x[T_LEN];
    __shared__ float  s_twr[T_LEN], s_twi[T_LEN];
    __shared__ float  s_Yr[32 * 65], s_Yi[32 * 65];
    __shared__ float2 s_tw64[64];
    int bc = blockIdx.x, tid = threadIdx.x;
    if (tid < PHA_NB / 2) g_cnt[bc][tid] = 0;        // reset fusion counters
    if (tid >= 64 && tid < 64 + NTB) g_tcnt[bc][tid - 64] = 0;
    for (int j = tid; j < T_LEN; j += 1024) {
        float s, c;
        sincospif((float)j * (1.0f / 1024.0f), &s, &c);
        s_twr[j] = c; s_twi[j] = s;
        s_x[j] = x[bc * T_LEN + j];
    }
    if (tid < 64) {
        float s, c;
        sincospif((float)tid * (1.0f / 32.0f), &s, &c);
        s_tw64[tid] = make_float2(c, -s);
    }
    __syncthreads();

    int b  = tid & 31;
    int mg = tid >> 5;
#pragma unroll
    for (int half = 0; half < 2; half++) {
        int m = mg + 32 * half;
        float ar = 0.f, ai = 0.f;
#pragma unroll 8
        for (int a = 0; a < 64; a++) {
            float  xv = s_x[(a << 5) + b];
            float2 w  = s_tw64[(m * a) & 63];
            ar = fmaf(xv, w.x, ar);
            ai = fmaf(xv, w.y, ai);
        }
        s_Yr[b * 65 + m] = ar;
        s_Yi[b * 65 + m] = ai;
    }
    __syncthreads();

    int k = tid;
    if (k < NKTOT) {
        int km = k & 63;
        float ar = 0.f, ai = 0.f;
#pragma unroll 8
        for (int b2 = 0; b2 < 32; b2++) {
            float yr = s_Yr[b2 * 65 + km];
            float yi = s_Yi[b2 * 65 + km];
            int id = (k * b2) & TMASK;
            float wr = s_twr[id], wi = s_twi[id];
            ar += yr * wr + yi * wi;
            ai += yi * wr - yr * wi;
        }
        g_Xf[bc][k] = make_float2(ar, ai);
    }
}

// ---------------- kernel 2: chunked prefix sweep + fused band tail ----------
// grid (12, 16, 8), block 128. Chunk z sweeps 80 k's (f32x2 packed).
// The LAST chunk block per (t-block, bc) runs the band tail inline.
__global__ __launch_bounds__(128, 8) void prefix_kernel() {
    __shared__ float2 s_XF[KCH];
    __shared__ float2 s_XG[KCH];
    __shared__ float  s_cumr[NCH][128];
    __shared__ float  s_cumi[NCH][128];
    __shared__ int    s_old;
    int bc  = blockIdx.y;
    int ch  = blockIdx.z;
    int k0  = ch * KCH;
    int tid = threadIdx.x;
    for (int j = tid; j < KCH; j += 128) {
        float2 X = g_Xf[bc][k0 + j];
        s_XF[j] = X;
        s_XG[j] = make_float2(-X.y, X.x);
    }
    __syncthreads();

    int tk = blockIdx.x * 128 + tid;
    int t  = EDGE + tk;
    float wr_, wi_;
    sincospif((float)t * (1.0f / 1024.0f), &wi_, &wr_);
    u64 Wr  = pk2(wr_, wr_);
    u64 Wi  = pk2(wi_, wi_);
    u64 WiN = pk2(-wi_, -wi_);
    float zr_, zi_;
    {
        int m = (k0 * t) & TMASK;
        sincospif((float)m * (1.0f / 1024.0f), &zi_, &zr_);
    }
    u64 Zr = pk2(zr_, zr_);
    u64 Zi = pk2(zi_, zi_);
    u64 Sa = 0ull, Sb = 0ull;

    int j    = c_tab.evstart[ch];
    int jend = c_tab.evstart[ch + 1];
    int nev  = (j < jend) ? c_tab.evk[j] : (1 << 30);

#pragma unroll
    for (int g = 0; g < KCH / 16; g++) {
        u64 Ca = 0ull, Cb = 0ull;
#pragma unroll
        for (int kk = 0; kk < 16; kk++) {
            int ks = g * 16 + kk;
            int k  = k0 + ks;
            u64 XF = *(const u64*)&s_XF[ks];
            u64 XG = *(const u64*)&s_XG[ks];
            Ca = fma2(Zr, XF, Ca);
            Cb = fma2(Zi, XG, Cb);
            if (k == nev) {
                do {
                    u64 tot = add2(add2(Sa, Ca), add2(Sb, Cb));
                    float vr, vi; up2(tot, vr, vi);
                    g_pref[bc][c_tab.evslot[j]][tk] = make_float2(vr, vi);
                    j++;
                    nev = (j < jend) ? c_tab.evk[j] : (1 << 30);
                } while (k == nev);
            }
            u64 nZr = fma2(Zi, WiN, mul2(Zr, Wr));
            u64 nZi = fma2(Zi, Wr,  mul2(Zr, Wi));
            Zr = nZr; Zi = nZi;
        }
        Sa = add2(Sa, Ca);
        Sb = add2(Sb, Cb);
    }
    if (ch < NCH - 1) {
        u64 tot = add2(Sa, Sb);
        float vr, vi; up2(tot, vr, vi);
        g_ctot[ch][bc][tk] = make_float2(vr, vi);
    }

    // ---- last-chunk-block-done: run band tail inline -------------------------
    __threadfence();
    if (tid == 0) s_old = atomicAdd(&g_tcnt[bc][blockIdx.x], 1);
    __syncthreads();
    if (s_old != NCH - 1) return;
    __threadfence();

    {
        float ar = 0.f, ai = 0.f;
        s_cumr[0][tid] = 0.f; s_cumi[0][tid] = 0.f;
#pragma unroll
        for (int c2 = 1; c2 < NCH; c2++) {
            float2 T = g_ctot[c2 - 1][bc][tk];
            ar += T.x; ai += T.y;
            s_cumr[c2][tid] = ar; s_cumi[c2][tid] = ai;
        }
    }
    __syncthreads();

    const float PIF    = 3.14159274101257324f;
    const float WIDTHF = (float)(2.0 * M_PI / (double)NBINS);
    float famp[AMP_NB];
#pragma unroll
    for (int b = 0; b < NBAND; b++) {
        float2 pa = g_pref[bc][2 * b][tk];
        float2 pb = g_pref[bc][2 * b + 1][tk];
        int ca = c_tab.cha[b], cb = c_tab.chb[b];
        float re = (pb.x + s_cumr[cb][tid]) - (pa.x + s_cumr[ca][tid]);
        float im = (pb.y + s_cumi[cb][tid]) - (pa.y + s_cumi[ca][tid]);
        if (b < PHA_NB) {
            float ang = atan2f(im, re);
            float q   = __fdiv_rn(ang + PIF, WIDTHF);
            int   idx = (int)floorf(q);
            idx = max(0, min(idx, NBINS - 1));
            g_pidx[bc][b][tk] = (unsigned char)idx;
        } else {
            famp[b - PHA_NB] = sqrtf(re * re + im * im);
        }
    }
    // write amp row (64B contiguous per thread; cols 30=count, 31=0)
    unsigned int* dst = (unsigned int*)&g_amp[bc][tk][0];
#pragma unroll
    for (int c2 = 0; c2 < 15; c2++) {
        __half2 h2 = __floats2half2_rn(famp[2 * c2], famp[2 * c2 + 1]);
        dst[c2] = *(unsigned int*)&h2;
    }
    {
        __half2 one = __floats2half2_rn(1.0f, 0.0f);
        dst[15] = *(unsigned int*)&one;
    }
}

// ---------------- kernel 3: binned sums + fused MI reduce --------------------
// grid (25, 16, 8), block 32 (1 warp), 9.6KB smem -> ~22 blocks/SM, one wave.
// lane = t-half(2) x channel-pair(16); 2 p's share each amp load.
__global__ __launch_bounds__(32) void mi_kernel(float* __restrict__ out) {
    __shared__ unsigned int s_idxw[2][TPB2 / 4];      // 384 B
    __shared__ float2 s_acc[2][NBINS][32];            // 9.2 KB
    __shared__ int s_old;
    int bc  = blockIdx.y;
    int px  = blockIdx.x;
    int p0  = px * 2;
    int z   = blockIdx.z;
    int lane = threadIdx.x;
    int c   = lane & 15;

    for (int pp = 0; pp < 2; pp++) {
        const unsigned int* src =
            (const unsigned int*)&g_pidx[bc][p0 + pp][z * TPB2];
        for (int j2 = lane; j2 < TPB2 / 4; j2 += 32) s_idxw[pp][j2] = src[j2];
    }
    {
        float4* a4 = (float4*)s_acc;
        for (int j2 = lane; j2 < 2 * NBINS * 32 / 2; j2 += 32)
            a4[j2] = make_float4(0.f, 0.f, 0.f, 0.f);
    }
    __syncthreads();

    const __half2* amp2 = (const __half2*)&g_amp[bc][z * TPB2][0];
    int tb = (lane >> 4) * (TPB2 / 2);                // 96 t per half

    int kp0 = -1, kp1 = -1;
    float2 run0 = make_float2(0.f, 0.f);
    float2 run1 = make_float2(0.f, 0.f);
    for (int i0 = 0; i0 < TPB2 / 2; i0 += 4) {
        float2 v[4];
#pragma unroll
        for (int i = 0; i < 4; i++)
            v[i] = __half22float2(amp2[(tb + i0 + i) * 16 + c]);
        unsigned int w0 = s_idxw[0][(tb + i0) >> 2];
        unsigned int w1 = s_idxw[1][(tb + i0) >> 2];
#pragma unroll
        for (int i = 0; i < 4; i++) {
            int b0 = (w0 >> (8 * i)) & 255;
            int b1 = (w1 >> (8 * i)) & 255;
            if (b0 != kp0) {
                if (kp0 >= 0) {
                    float2 a = s_acc[0][kp0][lane];
                    a.x += run0.x; a.y += run0.y;
                    s_acc[0][kp0][lane] = a;
                }
                kp0 = b0; run0 = v[i];
            } else { run0.x += v[i].x; run0.y += v[i].y; }
            if (b1 != kp1) {
                if (kp1 >= 0) {
                    float2 a = s_acc[1][kp1][lane];
                    a.x += run1.x; a.y += run1.y;
                    s_acc[1][kp1][lane] = a;
                }
                kp1 = b1; run1 = v[i];
            } else { run1.x += v[i].x; run1.y += v[i].y; }
        }
    }
    {
        float2 a = s_acc[0][kp0][lane];
        a.x += run0.x; a.y += run0.y;
        s_acc[0][kp0][lane] = a;
        float2 b = s_acc[1][kp1][lane];
        b.x += run1.x; b.y += run1.y;
        s_acc[1][kp1][lane] = b;
    }
    __syncthreads();

    // merge t-half columns -> g_part[bc][p][z][k][16]
    for (int j2 = lane; j2 < 2 * NBINS * 16; j2 += 32) {
        int pp = j2 / (NBINS * 16);
        int r  = j2 % (NBINS * 16);
        int k  = r >> 4;
        int ch = r & 15;
        float2 a = s_acc[pp][k][ch];
        float2 b = s_acc[pp][k][ch + 16];
        g_part[bc][p0 + pp][z][k][ch] = make_float2(a.x + b.x, a.y + b.y);
    }

    // last-block-done reduce
    __threadfence();
    if (lane == 0) s_old = atomicAdd(&g_cnt[bc][px], 1);
    __syncthreads();
    if (s_old != TS2 - 1) return;
    __threadfence();

    const float LOG_NB = 2.8903717578961645f;
    int cl = lane & 15;
#pragma unroll
    for (int pp = 0; pp < 2; pp++) {
        int p = p0 + pp;
        float2 means[NBINS];
        float2 tot = make_float2(0.f, 0.f);
#pragma unroll
        for (int k = 0; k < NBINS; k++) {
            float2 s = make_float2(0.f, 0.f);
#pragma unroll
            for (int zz = 0; zz < TS2; zz++) {
                float2 a = g_part[bc][p][zz][k][cl];
                s.x += a.x; s.y += a.y;
            }
            float cnt = __shfl_sync(0xffffffffu, s.x, 15);
            float2 m;
            m.x = __fdiv_rn(s.x, fmaxf(cnt, 1e-9f));
            m.y = __fdiv_rn(s.y, fmaxf(cnt, 1e-9f));
            means[k] = m;
            tot.x += m.x; tot.y += m.y;
        }
        float2 denom = make_float2(fmaxf(tot.x, 1e-9f), fmaxf(tot.y, 1e-9f));
        float2 acc = make_float2(0.f, 0.f);
#pragma unroll
        for (int k = 0; k < NBINS; k++) {
            float prx = __fdiv_rn(means[k].x, denom.x);
            float pry = __fdiv_rn(means[k].y, denom.y);
            acc.x += prx * logf(prx + 1e-9f);
            acc.y += pry * logf(pry + 1e-9f);
        }
        if (lane < 15) {
            float* o = &out[(bc * PHA_NB + p) * AMP_NB];
            o[2 * lane]     = (LOG_NB + acc.x) / LOG_NB;
            o[2 * lane + 1] = (LOG_NB + acc.y) / LOG_NB;
        }
    }
}

// ---------------- launch -----------------------------------------------------
extern "C" void kernel_launch(void* const* d_in, const int* in_sizes, int n_in,
                              void* d_out, int out_size) {
    const float* x = (const float*)d_in[0];
    float* out = (float*)d_out;

    dft_kernel<<<NBC, 1024>>>(x);
    prefix_kernel<<<dim3(NTB, NBC, NCH), 128>>>();
    mi_kernel<<<dim3(PHA_NB / 2, NBC, TS2), 32>>>(out);
}

// round 9
// speedup vs baseline: 1.6476x; 1.6476x over previous
#include <cuda_runtime.h>
#include <cuda_fp16.h>
#include <math.h>

#define T_LEN   2048
#define TMASK   2047
#define NKEEP   1536
#define EDGE    256
#define NBC     16
#define NBAND   80
#define PHA_NB  50
#define AMP_NB  30
#define NBINS   18
#define NKTOT   640
#define NEV     160
#define KCH     80
#define NCH     8
#define TS2     4
#define TPB2    (NKEEP / TS2)   // 384 t per mi block
#define KB_DFT  (NKTOT / 4)     // 160 k per dft block

// ---------------- f32x2 packed helpers (sm_103a) -----------------------------
typedef unsigned long long u64;
__device__ __forceinline__ u64 pk2(float lo, float hi) {
    u64 d; asm("mov.b64 %0,{%1,%2};" : "=l"(d) : "f"(lo), "f"(hi)); return d;
}
__device__ __forceinline__ void up2(u64 v, float& lo, float& hi) {
    asm("mov.b64 {%0,%1},%2;" : "=f"(lo), "=f"(hi) : "l"(v));
}
__device__ __forceinline__ u64 fma2(u64 a, u64 b, u64 c) {
    u64 d; asm("fma.rn.f32x2 %0,%1,%2,%3;" : "=l"(d) : "l"(a), "l"(b), "l"(c)); return d;
}
__device__ __forceinline__ u64 add2(u64 a, u64 b) {
    u64 d; asm("add.rn.f32x2 %0,%1,%2;" : "=l"(d) : "l"(a), "l"(b)); return d;
}
__device__ __forceinline__ u64 mul2(u64 a, u64 b) {
    u64 d; asm("mul.rn.f32x2 %0,%1,%2;" : "=l"(d) : "l"(a), "l"(b)); return d;
}

// ---------------- compile-time tables ---------------------------------------
struct Tables {
    int evk[NEV];
    int evslot[NEV];
    int evstart[NCH + 1];
    int cha[NBAND];
    int chb[NBAND];
};

constexpr Tables make_tables() {
    Tables tb{};
    int klo[NBAND] = {}, khi[NBAND] = {};
    for (int b = 0; b < NBAND; b++) {
        double lo_d = 0.0, hi_d = 0.0;
        if (b < PHA_NB) {
            double step = 18.0 / 49.0;
            double mid  = (b == PHA_NB - 1) ? 20.0 : ((double)b * step + 2.0);
            lo_d = mid * 0.75; hi_d = mid * 1.25;
        } else {
            int i = b - PHA_NB;
            double step = (141.0 - 60.0) / 29.0;
            double mid  = (i == AMP_NB - 1) ? 141.0 : ((double)i * step + 60.0);
            lo_d = mid * 0.875; hi_d = mid * 1.125;
        }
        float lo = (float)lo_d, hi = (float)hi_d;
        int kl = -1, kh = -2;
        for (int k = 1; k < NKTOT; k++) {
            float f = (float)k * 0.25f;
            if (f >= lo && f <= hi) { if (kl < 0) kl = k; kh = k; }
        }
        klo[b] = kl; khi[b] = kh;
        tb.cha[b] = (kl - 1) / KCH;
        tb.chb[b] = kh / KCH;
    }
    int key[NEV] = {}, slot[NEV] = {};
    for (int e = 0; e < NEV; e++) {
        int b = e >> 1, type = e & 1;
        key[e]  = type ? khi[b] : (klo[b] - 1);
        slot[e] = e;
    }
    for (int i = 1; i < NEV; i++) {
        int k2 = key[i], s2 = slot[i], j = i - 1;
        while (j >= 0 && key[j] > k2) { key[j+1] = key[j]; slot[j+1] = slot[j]; j--; }
        key[j+1] = k2; slot[j+1] = s2;
    }
    for (int e = 0; e < NEV; e++) { tb.evk[e] = key[e]; tb.evslot[e] = slot[e]; }
    for (int c = 0; c <= NCH; c++) {
        int s = 0;
        while (s < NEV && key[s] < c * KCH) s++;
        tb.evstart[c] = s;
    }
    return tb;
}
__constant__ Tables c_tab = make_tables();

// ---------------- scratch -----------------------------------------------------
__device__ float2        g_Xf[NBC][NKTOT];
__device__ float2        g_pref[NBC][NEV][NKEEP];
__device__ float2        g_ctot[NCH - 1][NBC][NKEEP];
__device__ unsigned char g_pidx[NBC][PHA_NB][NKEEP];
__device__ __half2       g_ampT[NBC][16][NKEEP];     // channel-pair major!
__device__ float2        g_part[NBC][PHA_NB][TS2][NBINS][16];
__device__ int           g_cnt[NBC][PHA_NB / 2];

// ---------------- kernel 1: fused 2-stage DFT, B split in quarters ----------
// grid (16, 4), block 1024. Stage A replicated per block (cheap); stage B
// covers k in [by*160, by*160+160).
__global__ __launch_bounds__(1024) void dft_kernel(const float* __restrict__ x) {
    __shared__ float  s_x[T_LEN];
    __shared__ float  s_twr[T_LEN], s_twi[T_LEN];
    __shared__ float  s_Yr[32 * 65], s_Yi[32 * 65];
    __shared__ float2 s_tw64[64];
    int bc = blockIdx.x, by = blockIdx.y, tid = threadIdx.x;
    if (by == 0 && tid < PHA_NB / 2) g_cnt[bc][tid] = 0;   // reset mi counters
    for (int j = tid; j < T_LEN; j += 1024) {
        float s, c;
        sincospif((float)j * (1.0f / 1024.0f), &s, &c);
        s_twr[j] = c; s_twi[j] = s;
        s_x[j] = x[bc * T_LEN + j];
    }
    if (tid < 64) {
        float s, c;
        sincospif((float)tid * (1.0f / 32.0f), &s, &c);
        s_tw64[tid] = make_float2(c, -s);
    }
    __syncthreads();

    int b  = tid & 31;
    int mg = tid >> 5;
#pragma unroll
    for (int half = 0; half < 2; half++) {
        int m = mg + 32 * half;
        float ar = 0.f, ai = 0.f;
#pragma unroll 8
        for (int a = 0; a < 64; a++) {
            float  xv = s_x[(a << 5) + b];
            float2 w  = s_tw64[(m * a) & 63];
            ar = fmaf(xv, w.x, ar);
            ai = fmaf(xv, w.y, ai);
        }
        s_Yr[b * 65 + m] = ar;
        s_Yi[b * 65 + m] = ai;
    }
    __syncthreads();

    if (tid < KB_DFT) {
        int k  = by * KB_DFT + tid;
        int km = k & 63;
        float ar = 0.f, ai = 0.f;
#pragma unroll 8
        for (int b2 = 0; b2 < 32; b2++) {
            float yr = s_Yr[b2 * 65 + km];
            float yi = s_Yi[b2 * 65 + km];
            int id = (k * b2) & TMASK;
            float wr = s_twr[id], wi = s_twi[id];
            ar += yr * wr + yi * wi;
            ai += yi * wr - yr * wi;
        }
        g_Xf[bc][k] = make_float2(ar, ai);
    }
}

// ---------------- kernel 2: chunked prefix sweep, f32x2 packed --------------
__global__ __launch_bounds__(128) void prefix_kernel() {
    __shared__ float2 s_XF[KCH];
    __shared__ float2 s_XG[KCH];
    int bc  = blockIdx.y;
    int ch  = blockIdx.z;
    int k0  = ch * KCH;
    int tid = threadIdx.x;
    for (int j = tid; j < KCH; j += 128) {
        float2 X = g_Xf[bc][k0 + j];
        s_XF[j] = X;
        s_XG[j] = make_float2(-X.y, X.x);
    }
    __syncthreads();

    int tk = blockIdx.x * 128 + tid;
    int t  = EDGE + tk;
    float wr_, wi_;
    sincospif((float)t * (1.0f / 1024.0f), &wi_, &wr_);
    u64 Wr  = pk2(wr_, wr_);
    u64 Wi  = pk2(wi_, wi_);
    u64 WiN = pk2(-wi_, -wi_);
    float zr_, zi_;
    {
        int m = (k0 * t) & TMASK;
        sincospif((float)m * (1.0f / 1024.0f), &zi_, &zr_);
    }
    u64 Zr = pk2(zr_, zr_);
    u64 Zi = pk2(zi_, zi_);
    u64 Sa = 0ull, Sb = 0ull;

    int j    = c_tab.evstart[ch];
    int jend = c_tab.evstart[ch + 1];
    int nev  = (j < jend) ? c_tab.evk[j] : (1 << 30);

#pragma unroll
    for (int g = 0; g < KCH / 16; g++) {
        u64 Ca = 0ull, Cb = 0ull;
#pragma unroll
        for (int kk = 0; kk < 16; kk++) {
            int ks = g * 16 + kk;
            int k  = k0 + ks;
            u64 XF = *(const u64*)&s_XF[ks];
            u64 XG = *(const u64*)&s_XG[ks];
            Ca = fma2(Zr, XF, Ca);
            Cb = fma2(Zi, XG, Cb);
            if (k == nev) {
                do {
                    u64 tot = add2(add2(Sa, Ca), add2(Sb, Cb));
                    float vr, vi; up2(tot, vr, vi);
                    g_pref[bc][c_tab.evslot[j]][tk] = make_float2(vr, vi);
                    j++;
                    nev = (j < jend) ? c_tab.evk[j] : (1 << 30);
                } while (k == nev);
            }
            u64 nZr = fma2(Zi, WiN, mul2(Zr, Wr));
            u64 nZi = fma2(Zi, Wr,  mul2(Zr, Wi));
            Zr = nZr; Zi = nZi;
        }
        Sa = add2(Sa, Ca);
        Sb = add2(Sb, Cb);
    }
    if (ch < NCH - 1) {
        u64 tot = add2(Sa, Sb);
        float vr, vi; up2(tot, vr, vi);
        g_ctot[ch][bc][tk] = make_float2(vr, vi);
    }
}

// ---------------- kernel 3: band tail -- snapshots + chunk-prefix -----------
// grid (12, 16, 5), block 128; band group z covers 16 bands.
// Amp written to channel-pair-major g_ampT (coalesced per pair).
__global__ __launch_bounds__(128) void tail_kernel() {
    __shared__ float s_cumr[NCH][129], s_cumi[NCH][129];
    int bc  = blockIdx.y;
    int bg  = blockIdx.z;
    int tid = threadIdx.x;
    int tk  = blockIdx.x * 128 + tid;

    float cr = 0.f, ci = 0.f;
    s_cumr[0][tid] = 0.f; s_cumi[0][tid] = 0.f;
#pragma unroll
    for (int ch = 1; ch < NCH; ch++) {
        float2 T = g_ctot[ch - 1][bc][tk];
        cr += T.x; ci += T.y;
        s_cumr[ch][tid] = cr; s_cumi[ch][tid] = ci;
    }
    __syncthreads();

    const float PIF    = 3.14159274101257324f;
    const float WIDTHF = (float)(2.0 * M_PI / (double)NBINS);
    float aprev = 0.f;
#pragma unroll
    for (int bb = 0; bb < 16; bb++) {
        int b = bg * 16 + bb;
        float2 pa = g_pref[bc][2 * b][tk];
        float2 pb = g_pref[bc][2 * b + 1][tk];
        int ca = c_tab.cha[b], cb = c_tab.chb[b];
        float re = (pb.x + s_cumr[cb][tid]) - (pa.x + s_cumr[ca][tid]);
        float im = (pb.y + s_cumi[cb][tid]) - (pa.y + s_cumi[ca][tid]);
        if (b < PHA_NB) {
            float ang = atan2f(im, re);
            float q   = __fdiv_rn(ang + PIF, WIDTHF);
            int   idx = (int)floorf(q);
            idx = max(0, min(idx, NBINS - 1));
            g_pidx[bc][b][tk] = (unsigned char)idx;
        } else {
            int a = b - PHA_NB;
            float v = sqrtf(re * re + im * im);
            if (a & 1) {
                g_ampT[bc][a >> 1][tk] = __floats2half2_rn(aprev, v);
            } else {
                aprev = v;
            }
        }
    }
    if (bg == 4) {          // count channel-pair 15: (1, 0)
        g_ampT[bc][15][tk] = __floats2half2_rn(1.0f, 0.0f);
    }
}

// ---------------- kernel 4: binned sums + fused MI reduce --------------------
// grid (25, 16, 4), block 64 (2 warps). lane = t-half(2) x channel-pair(16);
// amp loaded as LDG.128 spanning 8 t (channel-major layout) -> 12 wide loads
// per 96-t chain instead of 96 scalar loads. 2 p's share each amp load.
__global__ __launch_bounds__(64) void mi_kernel(float* __restrict__ out) {
    __shared__ unsigned int s_idxw[2][TPB2 / 4];      // 768 B
    __shared__ float2 s_acc[2][2][NBINS][32];         // 18.4 KB
    __shared__ int s_old;
    int bc  = blockIdx.y;
    int px  = blockIdx.x;
    int p0  = px * 2;
    int z   = blockIdx.z;
    int tid = threadIdx.x;
    int w   = tid >> 5;
    int lane = tid & 31;
    int c   = lane & 15;

    for (int pp = 0; pp < 2; pp++) {
        const unsigned int* src =
            (const unsigned int*)&g_pidx[bc][p0 + pp][z * TPB2];
        for (int j = tid; j < TPB2 / 4; j += 64) s_idxw[pp][j] = src[j];
    }
    {
        float4* a4 = (float4*)s_acc;
        for (int j = tid; j < 2 * 2 * NBINS * 32 / 2; j += 64)
            a4[j] = make_float4(0.f, 0.f, 0.f, 0.f);
    }
    __syncthreads();

    const __half2* arow = &g_ampT[bc][c][z * TPB2];
    int tb = w * 192 + (lane >> 4) * 96;              // local t base, 96 steps

    int kp0 = -1, kp1 = -1;
    float2 run0 = make_float2(0.f, 0.f);
    float2 run1 = make_float2(0.f, 0.f);
    for (int i0 = 0; i0 < 96; i0 += 8) {
        uint4 q = *(const uint4*)&arow[tb + i0];      // 8 t as 4 half2-pairs
        float2 v[8];
        {
            __half2 h;
            *(unsigned int*)&h = q.x;         float2 f = __half22float2(h);
            v[0] = f; v[1] = make_float2(0,0);
            // unpack: q.x holds t0,t1 halves for channel pair? NO:
        }
        // g_ampT row is __half2 per t: q.{x,y,z,w} = t pairs (t0t0?),
        // each uint = one half2 = (ch2c, ch2c+1) at one t. So 4 t per uint4.
        // Need 8 t -> two uint4 loads.
        {
            __half2 h0, h1, h2, h3;
            *(unsigned int*)&h0 = q.x; *(unsigned int*)&h1 = q.y;
            *(unsigned int*)&h2 = q.z; *(unsigned int*)&h3 = q.w;
            v[0] = __half22float2(h0); v[1] = __half22float2(h1);
            v[2] = __half22float2(h2); v[3] = __half22float2(h3);
        }
        uint4 q2 = *(const uint4*)&arow[tb + i0 + 4];
        {
            __half2 h0, h1, h2, h3;
            *(unsigned int*)&h0 = q2.x; *(unsigned int*)&h1 = q2.y;
            *(unsigned int*)&h2 = q2.z; *(unsigned int*)&h3 = q2.w;
            v[4] = __half22float2(h0); v[5] = __half22float2(h1);
            v[6] = __half22float2(h2); v[7] = __half22float2(h3);
        }
        unsigned int w0a = s_idxw[0][(tb + i0) >> 2];
        unsigned int w0b = s_idxw[0][((tb + i0) >> 2) + 1];
        unsigned int w1a = s_idxw[1][(tb + i0) >> 2];
        unsigned int w1b = s_idxw[1][((tb + i0) >> 2) + 1];
#pragma unroll
        for (int i = 0; i < 8; i++) {
            int b0 = ((i < 4 ? w0a : w0b) >> (8 * (i & 3))) & 255;
            int b1 = ((i < 4 ? w1a : w1b) >> (8 * (i & 3))) & 255;
            if (b0 != kp0) {
                if (kp0 >= 0) {
                    float2 a = s_acc[w][0][kp0][lane];
                    a.x += run0.x; a.y += run0.y;
                    s_acc[w][0][kp0][lane] = a;
                }
                kp0 = b0; run0 = v[i];
            } else { run0.x += v[i].x; run0.y += v[i].y; }
            if (b1 != kp1) {
                if (kp1 >= 0) {
                    float2 a = s_acc[w][1][kp1][lane];
                    a.x += run1.x; a.y += run1.y;
                    s_acc[w][1][kp1][lane] = a;
                }
                kp1 = b1; run1 = v[i];
            } else { run1.x += v[i].x; run1.y += v[i].y; }
        }
    }
    {
        float2 a = s_acc[w][0][kp0][lane];
        a.x += run0.x; a.y += run0.y;
        s_acc[w][0][kp0][lane] = a;
        float2 b = s_acc[w][1][kp1][lane];
        b.x += run1.x; b.y += run1.y;
        s_acc[w][1][kp1][lane] = b;
    }
    __syncthreads();

    // merge warps + t-half columns -> g_part[bc][p][z][k][16]
    for (int j = tid; j < 2 * NBINS * 16; j += 64) {
        int pp = j / (NBINS * 16);
        int r  = j % (NBINS * 16);
        int k  = r >> 4;
        int ch = r & 15;
        float2 acc = make_float2(0.f, 0.f);
#pragma unroll
        for (int w2 = 0; w2 < 2; w2++) {
            float2 a = s_acc[w2][pp][k][ch];
            float2 b = s_acc[w2][pp][k][ch + 16];
            acc.x += a.x + b.x;
            acc.y += a.y + b.y;
        }
        g_part[bc][p0 + pp][z][k][ch] = acc;
    }

    // last-block-done reduce
    __threadfence();
    if (tid == 0) s_old = atomicAdd(&g_cnt[bc][px], 1);
    __syncthreads();
    if (s_old != TS2 - 1) return;
    __threadfence();

    int p  = p0 + w;                    // warp w -> its p
    int cl = lane & 15;
    float2 means[NBINS];
    float2 tot = make_float2(0.f, 0.f);
#pragma unroll
    for (int k = 0; k < NBINS; k++) {
        float2 s = make_float2(0.f, 0.f);
#pragma unroll
        for (int zz = 0; zz < TS2; zz++) {
            float2 a = g_part[bc][p][zz][k][cl];
            s.x += a.x; s.y += a.y;
        }
        float cnt = __shfl_sync(0xffffffffu, s.x, 15);
        float2 m;
        m.x = __fdiv_rn(s.x, fmaxf(cnt, 1e-9f));
        m.y = __fdiv_rn(s.y, fmaxf(cnt, 1e-9f));
        means[k] = m;
        tot.x += m.x; tot.y += m.y;
    }
    float2 denom = make_float2(fmaxf(tot.x, 1e-9f), fmaxf(tot.y, 1e-9f));
    float2 acc = make_float2(0.f, 0.f);
#pragma unroll
    for (int k = 0; k < NBINS; k++) {
        float prx = __fdiv_rn(means[k].x, denom.x);
        float pry = __fdiv_rn(means[k].y, denom.y);
        acc.x += prx * logf(prx + 1e-9f);
        acc.y += pry * logf(pry + 1e-9f);
    }
    const float LOG_NB = 2.8903717578961645f;
    if (lane < 15) {
        float* o = &out[(bc * PHA_NB + p) * AMP_NB];
        o[2 * lane]     = (LOG_NB + acc.x) / LOG_NB;
        o[2 * lane + 1] = (LOG_NB + acc.y) / LOG_NB;
    }
}

// ---------------- launch -----------------------------------------------------
extern "C" void kernel_launch(void* const* d_in, const int* in_sizes, int n_in,
                              void* d_out, int out_size) {
    const float* x = (const float*)d_in[0];
    float* out = (float*)d_out;

    dft_kernel<<<dim3(NBC, 4), 1024>>>(x);
    prefix_kernel<<<dim3(NKEEP / 128, NBC, NCH), 128>>>();
    tail_kernel<<<dim3(NKEEP / 128, NBC, 5), 128>>>();
    mi_kernel<<<dim3(PHA_NB / 2, NBC, TS2), 64>>>(out);
}

// round 10
// speedup vs baseline: 1.8023x; 1.0939x over previous
#include <cuda_runtime.h>
#include <cuda_fp16.h>
#include <math.h>

#define T_LEN   2048
#define TMASK   2047
#define NKEEP   1536
#define EDGE    256
#define NBC     16
#define NBAND   80
#define PHA_NB  50
#define AMP_NB  30
#define NBINS   18
#define NKTOT   640
#define NEV     160
#define KCH     80
#define NCH     8
#define KB_DFT  (NKTOT / 4)     // 160 k per dft block

// ---------------- f32x2 packed helpers (sm_103a) -----------------------------
typedef unsigned long long u64;
__device__ __forceinline__ u64 pk2(float lo, float hi) {
    u64 d; asm("mov.b64 %0,{%1,%2};" : "=l"(d) : "f"(lo), "f"(hi)); return d;
}
__device__ __forceinline__ void up2(u64 v, float& lo, float& hi) {
    asm("mov.b64 {%0,%1},%2;" : "=f"(lo), "=f"(hi) : "l"(v));
}
__device__ __forceinline__ u64 fma2(u64 a, u64 b, u64 c) {
    u64 d; asm("fma.rn.f32x2 %0,%1,%2,%3;" : "=l"(d) : "l"(a), "l"(b), "l"(c)); return d;
}
__device__ __forceinline__ u64 add2(u64 a, u64 b) {
    u64 d; asm("add.rn.f32x2 %0,%1,%2;" : "=l"(d) : "l"(a), "l"(b)); return d;
}
__device__ __forceinline__ u64 mul2(u64 a, u64 b) {
    u64 d; asm("mul.rn.f32x2 %0,%1,%2;" : "=l"(d) : "l"(a), "l"(b)); return d;
}

// ---------------- compile-time tables ---------------------------------------
struct Tables {
    int evk[NEV];
    int evslot[NEV];
    int evstart[NCH + 1];
    int cha[NBAND];
    int chb[NBAND];
};

constexpr Tables make_tables() {
    Tables tb{};
    int klo[NBAND] = {}, khi[NBAND] = {};
    for (int b = 0; b < NBAND; b++) {
        double lo_d = 0.0, hi_d = 0.0;
        if (b < PHA_NB) {
            double step = 18.0 / 49.0;
            double mid  = (b == PHA_NB - 1) ? 20.0 : ((double)b * step + 2.0);
            lo_d = mid * 0.75; hi_d = mid * 1.25;
        } else {
            int i = b - PHA_NB;
            double step = (141.0 - 60.0) / 29.0;
            double mid  = (i == AMP_NB - 1) ? 141.0 : ((double)i * step + 60.0);
            lo_d = mid * 0.875; hi_d = mid * 1.125;
        }
        float lo = (float)lo_d, hi = (float)hi_d;
        int kl = -1, kh = -2;
        for (int k = 1; k < NKTOT; k++) {
            float f = (float)k * 0.25f;
            if (f >= lo && f <= hi) { if (kl < 0) kl = k; kh = k; }
        }
        klo[b] = kl; khi[b] = kh;
        tb.cha[b] = (kl - 1) / KCH;
        tb.chb[b] = kh / KCH;
    }
    int key[NEV] = {}, slot[NEV] = {};
    for (int e = 0; e < NEV; e++) {
        int b = e >> 1, type = e & 1;
        key[e]  = type ? khi[b] : (klo[b] - 1);
        slot[e] = e;
    }
    for (int i = 1; i < NEV; i++) {
        int k2 = key[i], s2 = slot[i], j = i - 1;
        while (j >= 0 && key[j] > k2) { key[j+1] = key[j]; slot[j+1] = slot[j]; j--; }
        key[j+1] = k2; slot[j+1] = s2;
    }
    for (int e = 0; e < NEV; e++) { tb.evk[e] = key[e]; tb.evslot[e] = slot[e]; }
    for (int c = 0; c <= NCH; c++) {
        int s = 0;
        while (s < NEV && key[s] < c * KCH) s++;
        tb.evstart[c] = s;
    }
    return tb;
}
__constant__ Tables c_tab = make_tables();

// ---------------- scratch -----------------------------------------------------
__device__ float2        g_Xf[NBC][NKTOT];
__device__ float2        g_pref[NBC][NEV][NKEEP];
__device__ float2        g_ctot[NCH - 1][NBC][NKEEP];
__device__ unsigned char g_pidx[NBC][PHA_NB][NKEEP];
__device__ __half        g_ampH[NBC][32][NKEEP];     // channel-major; ch30=1, ch31=0

// ---------------- kernel 1: fused 2-stage DFT, B split in quarters ----------
__global__ __launch_bounds__(1024) void dft_kernel(const float* __restrict__ x) {
    __shared__ float  s_x[T_LEN];
    __shared__ float  s_twr[T_LEN], s_twi[T_LEN];
    __shared__ float  s_Yr[32 * 65], s_Yi[32 * 65];
    __shared__ float2 s_tw64[64];
    int bc = blockIdx.x, by = blockIdx.y, tid = threadIdx.x;
    for (int j = tid; j < T_LEN; j += 1024) {
        float s, c;
        sincospif((float)j * (1.0f / 1024.0f), &s, &c);
        s_twr[j] = c; s_twi[j] = s;
        s_x[j] = x[bc * T_LEN + j];
    }
    if (tid < 64) {
        float s, c;
        sincospif((float)tid * (1.0f / 32.0f), &s, &c);
        s_tw64[tid] = make_float2(c, -s);
    }
    __syncthreads();

    int b  = tid & 31;
    int mg = tid >> 5;
#pragma unroll
    for (int half = 0; half < 2; half++) {
        int m = mg + 32 * half;
        float ar = 0.f, ai = 0.f;
#pragma unroll 8
        for (int a = 0; a < 64; a++) {
            float  xv = s_x[(a << 5) + b];
            float2 w  = s_tw64[(m * a) & 63];
            ar = fmaf(xv, w.x, ar);
            ai = fmaf(xv, w.y, ai);
        }
        s_Yr[b * 65 + m] = ar;
        s_Yi[b * 65 + m] = ai;
    }
    __syncthreads();

    if (tid < KB_DFT) {
        int k  = by * KB_DFT + tid;
        int km = k & 63;
        float ar = 0.f, ai = 0.f;
#pragma unroll 8
        for (int b2 = 0; b2 < 32; b2++) {
            float yr = s_Yr[b2 * 65 + km];
            float yi = s_Yi[b2 * 65 + km];
            int id = (k * b2) & TMASK;
            float wr = s_twr[id], wi = s_twi[id];
            ar += yr * wr + yi * wi;
            ai += yi * wr - yr * wi;
        }
        g_Xf[bc][k] = make_float2(ar, ai);
    }
}

// ---------------- kernel 2: chunked prefix sweep, f32x2 packed --------------
__global__ __launch_bounds__(128) void prefix_kernel() {
    __shared__ float2 s_XF[KCH];
    __shared__ float2 s_XG[KCH];
    int bc  = blockIdx.y;
    int ch  = blockIdx.z;
    int k0  = ch * KCH;
    int tid = threadIdx.x;
    for (int j = tid; j < KCH; j += 128) {
        float2 X = g_Xf[bc][k0 + j];
        s_XF[j] = X;
        s_XG[j] = make_float2(-X.y, X.x);
    }
    __syncthreads();

    int tk = blockIdx.x * 128 + tid;
    int t  = EDGE + tk;
    float wr_, wi_;
    sincospif((float)t * (1.0f / 1024.0f), &wi_, &wr_);
    u64 Wr  = pk2(wr_, wr_);
    u64 Wi  = pk2(wi_, wi_);
    u64 WiN = pk2(-wi_, -wi_);
    float zr_, zi_;
    {
        int m = (k0 * t) & TMASK;
        sincospif((float)m * (1.0f / 1024.0f), &zi_, &zr_);
    }
    u64 Zr = pk2(zr_, zr_);
    u64 Zi = pk2(zi_, zi_);
    u64 Sa = 0ull, Sb = 0ull;

    int j    = c_tab.evstart[ch];
    int jend = c_tab.evstart[ch + 1];
    int nev  = (j < jend) ? c_tab.evk[j] : (1 << 30);

#pragma unroll
    for (int g = 0; g < KCH / 16; g++) {
        u64 Ca = 0ull, Cb = 0ull;
#pragma unroll
        for (int kk = 0; kk < 16; kk++) {
            int ks = g * 16 + kk;
            int k  = k0 + ks;
            u64 XF = *(const u64*)&s_XF[ks];
            u64 XG = *(const u64*)&s_XG[ks];
            Ca = fma2(Zr, XF, Ca);
            Cb = fma2(Zi, XG, Cb);
            if (k == nev) {
                do {
                    u64 tot = add2(add2(Sa, Ca), add2(Sb, Cb));
                    float vr, vi; up2(tot, vr, vi);
                    g_pref[bc][c_tab.evslot[j]][tk] = make_float2(vr, vi);
                    j++;
                    nev = (j < jend) ? c_tab.evk[j] : (1 << 30);
                } while (k == nev);
            }
            u64 nZr = fma2(Zi, WiN, mul2(Zr, Wr));
            u64 nZi = fma2(Zi, Wr,  mul2(Zr, Wi));
            Zr = nZr; Zi = nZi;
        }
        Sa = add2(Sa, Ca);
        Sb = add2(Sb, Cb);
    }
    if (ch < NCH - 1) {
        u64 tot = add2(Sa, Sb);
        float vr, vi; up2(tot, vr, vi);
        g_ctot[ch][bc][tk] = make_float2(vr, vi);
    }
}

// ---------------- kernel 3: band tail -- snapshots + chunk-prefix -----------
// grid (12, 16, 5), block 128. Amp written channel-major fp16 (coalesced).
__global__ __launch_bounds__(128) void tail_kernel() {
    __shared__ float s_cumr[NCH][129], s_cumi[NCH][129];
    int bc  = blockIdx.y;
    int bg  = blockIdx.z;
    int tid = threadIdx.x;
    int tk  = blockIdx.x * 128 + tid;

    float cr = 0.f, ci = 0.f;
    s_cumr[0][tid] = 0.f; s_cumi[0][tid] = 0.f;
#pragma unroll
    for (int ch = 1; ch < NCH; ch++) {
        float2 T = g_ctot[ch - 1][bc][tk];
        cr += T.x; ci += T.y;
        s_cumr[ch][tid] = cr; s_cumi[ch][tid] = ci;
    }
    __syncthreads();

    const float PIF    = 3.14159274101257324f;
    const float WIDTHF = (float)(2.0 * M_PI / (double)NBINS);
#pragma unroll
    for (int bb = 0; bb < 16; bb++) {
        int b = bg * 16 + bb;
        float2 pa = g_pref[bc][2 * b][tk];
        float2 pb = g_pref[bc][2 * b + 1][tk];
        int ca = c_tab.cha[b], cb = c_tab.chb[b];
        float re = (pb.x + s_cumr[cb][tid]) - (pa.x + s_cumr[ca][tid]);
        float im = (pb.y + s_cumi[cb][tid]) - (pa.y + s_cumi[ca][tid]);
        if (b < PHA_NB) {
            float ang = atan2f(im, re);
            float q   = __fdiv_rn(ang + PIF, WIDTHF);
            int   idx = (int)floorf(q);
            idx = max(0, min(idx, NBINS - 1));
            g_pidx[bc][b][tk] = (unsigned char)idx;
        } else {
            int a = b - PHA_NB;
            g_ampH[bc][a][tk] = __float2half_rn(sqrtf(re * re + im * im));
        }
    }
    if (bg == 4) {                      // count row + zero pad row
        g_ampH[bc][30][tk] = __float2half_rn(1.0f);
        g_ampH[bc][31][tk] = __float2half_rn(0.0f);
    }
}

// ---------------- kernel 4: binned sums via HMMA + MI ------------------------
// grid (50, 16), block 128 (4 warps, k-split). sums[ch][bin] =
// amp[ch][t] @ onehot[t][bin] with mma.sync.m16n8k16 (fp16 in, fp32 acc).
// M = 32 (ch 0-29 amp, 30 count, 31 pad), N = 24 (bins 0-17 + pad), K = 1536.
__global__ __launch_bounds__(128) void mi_mma_kernel(float* __restrict__ out) {
    __shared__ unsigned char s_bin[NKEEP];            // 1.5 KB
    __shared__ float s_red[3][24][32];                // 9.2 KB (warp partials)
    __shared__ float s_sum[32][25];                   // 3.2 KB
    int bc   = blockIdx.y;
    int p    = blockIdx.x;
    int tid  = threadIdx.x;
    int w    = tid >> 5;
    int lane = tid & 31;
    int gid  = lane >> 2;       // 0..7
    int tig  = lane & 3;        // 0..3

    {
        const uint4* src = (const uint4*)&g_pidx[bc][p][0];
        uint4* dst = (uint4*)s_bin;
        for (int j = tid; j < NKEEP / 16; j += 128) dst[j] = src[j];
    }
    __syncthreads();

    const __half* ampb = &g_ampH[bc][0][0];
    float d[6][4];
#pragma unroll
    for (int i = 0; i < 6; i++)
#pragma unroll
        for (int r = 0; r < 4; r++) d[i][r] = 0.f;

    int kbase = w * (NKEEP / 4);                      // 384 per warp
#pragma unroll 4
    for (int ks = 0; ks < (NKEEP / 4) / 16; ks++) {   // 24 k-steps
        int k0 = kbase + ks * 16;
        // ---- A fragments (amp), 2 m-tiles ----
        unsigned int a[2][4];
#pragma unroll
        for (int mt = 0; mt < 2; mt++) {
            const __half* r0 = ampb + (mt * 16 + gid) * NKEEP + k0 + 2 * tig;
            const __half* r1 = r0 + 8 * NKEEP;
            a[mt][0] = *(const unsigned int*)r0;
            a[mt][1] = *(const unsigned int*)r1;
            a[mt][2] = *(const unsigned int*)(r0 + 8);
            a[mt][3] = *(const unsigned int*)(r1 + 8);
        }
        // ---- bin bytes for B one-hot ----
        int t0 = k0 + 2 * tig;
        unsigned int blo = *(const unsigned short*)&s_bin[t0];
        unsigned int bhi = *(const unsigned short*)&s_bin[t0 + 8];
        int b00 = blo & 255, b01 = (blo >> 8) & 255;
        int b10 = bhi & 255, b11 = (bhi >> 8) & 255;
#pragma unroll
        for (int nt = 0; nt < 3; nt++) {
            int n = nt * 8 + gid;
            unsigned int bb0 = ((b00 == n) ? 0x3C00u : 0u)
                             | ((b01 == n) ? 0x3C000000u : 0u);
            unsigned int bb1 = ((b10 == n) ? 0x3C00u : 0u)
                             | ((b11 == n) ? 0x3C000000u : 0u);
#pragma unroll
            for (int mt = 0; mt < 2; mt++) {
                float* dd = d[mt * 3 + nt];
                asm volatile(
                    "mma.sync.aligned.m16n8k16.row.col.f32.f16.f16.f32 "
                    "{%0,%1,%2,%3},{%4,%5,%6,%7},{%8,%9},{%0,%1,%2,%3};"
                    : "+f"(dd[0]), "+f"(dd[1]), "+f"(dd[2]), "+f"(dd[3])
                    : "r"(a[mt][0]), "r"(a[mt][1]), "r"(a[mt][2]), "r"(a[mt][3]),
                      "r"(bb0), "r"(bb1));
            }
        }
    }

    // ---- reduce warp partials ----
    if (w > 0) {
#pragma unroll
        for (int i = 0; i < 6; i++)
#pragma unroll
            for (int r = 0; r < 4; r++)
                s_red[w - 1][i * 4 + r][lane] = d[i][r];
    }
    __syncthreads();
    if (w != 0) return;

#pragma unroll
    for (int i = 0; i < 6; i++)
#pragma unroll
        for (int r = 0; r < 4; r++)
            d[i][r] += s_red[0][i * 4 + r][lane]
                     + s_red[1][i * 4 + r][lane]
                     + s_red[2][i * 4 + r][lane];

    // scatter D -> s_sum[ch][bin]
#pragma unroll
    for (int mt = 0; mt < 2; mt++)
#pragma unroll
        for (int nt = 0; nt < 3; nt++) {
            float* dd = d[mt * 3 + nt];
            int ch0 = mt * 16 + gid;
            int cb  = nt * 8 + 2 * tig;
            s_sum[ch0][cb]     = dd[0];
            s_sum[ch0][cb + 1] = dd[1];
            s_sum[ch0 + 8][cb]     = dd[2];
            s_sum[ch0 + 8][cb + 1] = dd[3];
        }
    __syncwarp();

    // ---- MI per channel ----
    float means[NBINS];
    float tot = 0.f;
#pragma unroll
    for (int k = 0; k < NBINS; k++) {
        float cnt = s_sum[30][k];
        float s   = s_sum[lane & 31][k];
        float m   = __fdiv_rn(s, fmaxf(cnt, 1e-9f));
        means[k]  = m;
        tot      += m;
    }
    float denom = fmaxf(tot, 1e-9f);
    float acc = 0.f;
#pragma unroll
    for (int k = 0; k < NBINS; k++) {
        float pr = __fdiv_rn(means[k], denom);
        acc += pr * logf(pr + 1e-9f);
    }
    const float LOG_NB = 2.8903717578961645f;
    if (lane < AMP_NB)
        out[(bc * PHA_NB + p) * AMP_NB + lane] = (LOG_NB + acc) / LOG_NB;
}

// ---------------- launch -----------------------------------------------------
extern "C" void kernel_launch(void* const* d_in, const int* in_sizes, int n_in,
                              void* d_out, int out_size) {
    const float* x = (const float*)d_in[0];
    float* out = (float*)d_out;

    dft_kernel<<<dim3(NBC, 4), 1024>>>(x);
    prefix_kernel<<<dim3(NKEEP / 128, NBC, NCH), 128>>>();
    tail_kernel<<<dim3(NKEEP / 128, NBC, 5), 128>>>();
    mi_mma_kernel<<<dim3(PHA_NB, NBC), 128>>>(out);
}

// round 11
// speedup vs baseline: 1.9357x; 1.0740x over previous
#include <cuda_runtime.h>
#include <cuda_fp16.h>
#include <math.h>

#define T_LEN   2048
#define TMASK   2047
#define NKEEP   1536
#define EDGE    256
#define NBC     16
#define NBAND   80
#define PHA_NB  50
#define AMP_NB  30
#define NBINS   18
#define NKTOT   640
#define NEV     160
#define KCH     80
#define NCH     8
#define KB_DFT  (NKTOT / 4)     // 160 k per dft block
#define ZS      4               // K z-split in mi
#define KZB     (NKEEP / ZS)    // 384 t per mi block

// ---------------- f32x2 packed helpers (sm_103a) -----------------------------
typedef unsigned long long u64;
__device__ __forceinline__ u64 pk2(float lo, float hi) {
    u64 d; asm("mov.b64 %0,{%1,%2};" : "=l"(d) : "f"(lo), "f"(hi)); return d;
}
__device__ __forceinline__ void up2(u64 v, float& lo, float& hi) {
    asm("mov.b64 {%0,%1},%2;" : "=f"(lo), "=f"(hi) : "l"(v));
}
__device__ __forceinline__ u64 fma2(u64 a, u64 b, u64 c) {
    u64 d; asm("fma.rn.f32x2 %0,%1,%2,%3;" : "=l"(d) : "l"(a), "l"(b), "l"(c)); return d;
}
__device__ __forceinline__ u64 add2(u64 a, u64 b) {
    u64 d; asm("add.rn.f32x2 %0,%1,%2;" : "=l"(d) : "l"(a), "l"(b)); return d;
}
__device__ __forceinline__ u64 mul2(u64 a, u64 b) {
    u64 d; asm("mul.rn.f32x2 %0,%1,%2;" : "=l"(d) : "l"(a), "l"(b)); return d;
}

// ---------------- compile-time tables ---------------------------------------
struct Tables {
    int evk[NEV];
    int evslot[NEV];
    int evstart[NCH + 1];
    int cha[NBAND];
    int chb[NBAND];
};

constexpr Tables make_tables() {
    Tables tb{};
    int klo[NBAND] = {}, khi[NBAND] = {};
    for (int b = 0; b < NBAND; b++) {
        double lo_d = 0.0, hi_d = 0.0;
        if (b < PHA_NB) {
            double step = 18.0 / 49.0;
            double mid  = (b == PHA_NB - 1) ? 20.0 : ((double)b * step + 2.0);
            lo_d = mid * 0.75; hi_d = mid * 1.25;
        } else {
            int i = b - PHA_NB;
            double step = (141.0 - 60.0) / 29.0;
            double mid  = (i == AMP_NB - 1) ? 141.0 : ((double)i * step + 60.0);
            lo_d = mid * 0.875; hi_d = mid * 1.125;
        }
        float lo = (float)lo_d, hi = (float)hi_d;
        int kl = -1, kh = -2;
        for (int k = 1; k < NKTOT; k++) {
            float f = (float)k * 0.25f;
            if (f >= lo && f <= hi) { if (kl < 0) kl = k; kh = k; }
        }
        klo[b] = kl; khi[b] = kh;
        tb.cha[b] = (kl - 1) / KCH;
        tb.chb[b] = kh / KCH;
    }
    int key[NEV] = {}, slot[NEV] = {};
    for (int e = 0; e < NEV; e++) {
        int b = e >> 1, type = e & 1;
        key[e]  = type ? khi[b] : (klo[b] - 1);
        slot[e] = e;
    }
    for (int i = 1; i < NEV; i++) {
        int k2 = key[i], s2 = slot[i], j = i - 1;
        while (j >= 0 && key[j] > k2) { key[j+1] = key[j]; slot[j+1] = slot[j]; j--; }
        key[j+1] = k2; slot[j+1] = s2;
    }
    for (int e = 0; e < NEV; e++) { tb.evk[e] = key[e]; tb.evslot[e] = slot[e]; }
    for (int c = 0; c <= NCH; c++) {
        int s = 0;
        while (s < NEV && key[s] < c * KCH) s++;
        tb.evstart[c] = s;
    }
    return tb;
}
__constant__ Tables c_tab = make_tables();

// ---------------- scratch -----------------------------------------------------
__device__ float2        g_Xf[NBC][NKTOT];
__device__ float2        g_pref[NBC][NEV][NKEEP];
__device__ float2        g_ctot[NCH - 1][NBC][NKEEP];
__device__ unsigned char g_pidx[NBC][PHA_NB][NKEEP];
__device__ __half        g_ampH[NBC][32][NKEEP];     // channel-major; ch30=1, ch31=0
__device__ float         g_part[NBC][PHA_NB][ZS][24][32];
__device__ int           g_cnt[NBC][PHA_NB / 2];

// ---------------- kernel 1: fused 2-stage DFT, B split in quarters ----------
__global__ __launch_bounds__(1024) void dft_kernel(const float* __restrict__ x) {
    __shared__ float  s_x[T_LEN];
    __shared__ float  s_twr[T_LEN], s_twi[T_LEN];
    __shared__ float  s_Yr[32 * 65], s_Yi[32 * 65];
    __shared__ float2 s_tw64[64];
    int bc = blockIdx.x, by = blockIdx.y, tid = threadIdx.x;
    if (by == 0 && tid < PHA_NB / 2) g_cnt[bc][tid] = 0;   // reset mi counters
    for (int j = tid; j < T_LEN; j += 1024) {
        float s, c;
        sincospif((float)j * (1.0f / 1024.0f), &s, &c);
        s_twr[j] = c; s_twi[j] = s;
        s_x[j] = x[bc * T_LEN + j];
    }
    if (tid < 64) {
        float s, c;
        sincospif((float)tid * (1.0f / 32.0f), &s, &c);
        s_tw64[tid] = make_float2(c, -s);
    }
    __syncthreads();

    int b  = tid & 31;
    int mg = tid >> 5;
#pragma unroll
    for (int half = 0; half < 2; half++) {
        int m = mg + 32 * half;
        float ar = 0.f, ai = 0.f;
#pragma unroll 8
        for (int a = 0; a < 64; a++) {
            float  xv = s_x[(a << 5) + b];
            float2 w  = s_tw64[(m * a) & 63];
            ar = fmaf(xv, w.x, ar);
            ai = fmaf(xv, w.y, ai);
        }
        s_Yr[b * 65 + m] = ar;
        s_Yi[b * 65 + m] = ai;
    }
    __syncthreads();

    if (tid < KB_DFT) {
        int k  = by * KB_DFT + tid;
        int km = k & 63;
        float ar = 0.f, ai = 0.f;
#pragma unroll 8
        for (int b2 = 0; b2 < 32; b2++) {
            float yr = s_Yr[b2 * 65 + km];
            float yi = s_Yi[b2 * 65 + km];
            int id = (k * b2) & TMASK;
            float wr = s_twr[id], wi = s_twi[id];
            ar += yr * wr + yi * wi;
            ai += yi * wr - yr * wi;
        }
        g_Xf[bc][k] = make_float2(ar, ai);
    }
}

// ---------------- kernel 2: chunked prefix sweep, f32x2 packed --------------
__global__ __launch_bounds__(128) void prefix_kernel() {
    __shared__ float2 s_XF[KCH];
    __shared__ float2 s_XG[KCH];
    int bc  = blockIdx.y;
    int ch  = blockIdx.z;
    int k0  = ch * KCH;
    int tid = threadIdx.x;
    for (int j = tid; j < KCH; j += 128) {
        float2 X = g_Xf[bc][k0 + j];
        s_XF[j] = X;
        s_XG[j] = make_float2(-X.y, X.x);
    }
    __syncthreads();

    int tk = blockIdx.x * 128 + tid;
    int t  = EDGE + tk;
    float wr_, wi_;
    sincospif((float)t * (1.0f / 1024.0f), &wi_, &wr_);
    u64 Wr  = pk2(wr_, wr_);
    u64 Wi  = pk2(wi_, wi_);
    u64 WiN = pk2(-wi_, -wi_);
    float zr_, zi_;
    {
        int m = (k0 * t) & TMASK;
        sincospif((float)m * (1.0f / 1024.0f), &zi_, &zr_);
    }
    u64 Zr = pk2(zr_, zr_);
    u64 Zi = pk2(zi_, zi_);
    u64 Sa = 0ull, Sb = 0ull;

    int j    = c_tab.evstart[ch];
    int jend = c_tab.evstart[ch + 1];
    int nev  = (j < jend) ? c_tab.evk[j] : (1 << 30);

#pragma unroll
    for (int g = 0; g < KCH / 16; g++) {
        u64 Ca = 0ull, Cb = 0ull;
#pragma unroll
        for (int kk = 0; kk < 16; kk++) {
            int ks = g * 16 + kk;
            int k  = k0 + ks;
            u64 XF = *(const u64*)&s_XF[ks];
            u64 XG = *(const u64*)&s_XG[ks];
            Ca = fma2(Zr, XF, Ca);
            Cb = fma2(Zi, XG, Cb);
            if (k == nev) {
                do {
                    u64 tot = add2(add2(Sa, Ca), add2(Sb, Cb));
                    float vr, vi; up2(tot, vr, vi);
                    g_pref[bc][c_tab.evslot[j]][tk] = make_float2(vr, vi);
                    j++;
                    nev = (j < jend) ? c_tab.evk[j] : (1 << 30);
                } while (k == nev);
            }
            u64 nZr = fma2(Zi, WiN, mul2(Zr, Wr));
            u64 nZi = fma2(Zi, Wr,  mul2(Zr, Wi));
            Zr = nZr; Zi = nZi;
        }
        Sa = add2(Sa, Ca);
        Sb = add2(Sb, Cb);
    }
    if (ch < NCH - 1) {
        u64 tot = add2(Sa, Sb);
        float vr, vi; up2(tot, vr, vi);
        g_ctot[ch][bc][tk] = make_float2(vr, vi);
    }
}

// ---------------- kernel 3: band tail -- snapshots + chunk-prefix -----------
__global__ __launch_bounds__(128) void tail_kernel() {
    __shared__ float s_cumr[NCH][129], s_cumi[NCH][129];
    int bc  = blockIdx.y;
    int bg  = blockIdx.z;
    int tid = threadIdx.x;
    int tk  = blockIdx.x * 128 + tid;

    float cr = 0.f, ci = 0.f;
    s_cumr[0][tid] = 0.f; s_cumi[0][tid] = 0.f;
#pragma unroll
    for (int ch = 1; ch < NCH; ch++) {
        float2 T = g_ctot[ch - 1][bc][tk];
        cr += T.x; ci += T.y;
        s_cumr[ch][tid] = cr; s_cumi[ch][tid] = ci;
    }
    __syncthreads();

    const float PIF    = 3.14159274101257324f;
    const float WIDTHF = (float)(2.0 * M_PI / (double)NBINS);
#pragma unroll
    for (int bb = 0; bb < 16; bb++) {
        int b = bg * 16 + bb;
        float2 pa = g_pref[bc][2 * b][tk];
        float2 pb = g_pref[bc][2 * b + 1][tk];
        int ca = c_tab.cha[b], cb = c_tab.chb[b];
        float re = (pb.x + s_cumr[cb][tid]) - (pa.x + s_cumr[ca][tid]);
        float im = (pb.y + s_cumi[cb][tid]) - (pa.y + s_cumi[ca][tid]);
        if (b < PHA_NB) {
            float ang = atan2f(im, re);
            float q   = __fdiv_rn(ang + PIF, WIDTHF);
            int   idx = (int)floorf(q);
            idx = max(0, min(idx, NBINS - 1));
            g_pidx[bc][b][tk] = (unsigned char)idx;
        } else {
            int a = b - PHA_NB;
            g_ampH[bc][a][tk] = __float2half_rn(sqrtf(re * re + im * im));
        }
    }
    if (bg == 4) {                      // count row + zero pad row
        g_ampH[bc][30][tk] = __float2half_rn(1.0f);
        g_ampH[bc][31][tk] = __float2half_rn(0.0f);
    }
}

// ---------------- kernel 4: binned sums via HMMA, PTILE=2, z-split K --------
// grid (25, 16, 4), block 128 (4 warps). Each block: 2 p's share A fragments,
// K-chunk of 384 (96 per warp = 6 ksteps). Last z-block reduces + emits MI.
__global__ __launch_bounds__(128) void mi_mma_kernel(float* __restrict__ out) {
    __shared__ unsigned char s_bin[2][KZB];           // 768 B
    __shared__ float s_red[3][24][32];                // 9.2 KB
    __shared__ float s_sum[2][32][25];                // 6.4 KB
    __shared__ int s_old;
    int bc   = blockIdx.y;
    int px   = blockIdx.x;
    int p0   = px * 2;
    int z    = blockIdx.z;
    int tid  = threadIdx.x;
    int w    = tid >> 5;
    int lane = tid & 31;
    int gid  = lane >> 2;       // 0..7
    int tig  = lane & 3;        // 0..3

#pragma unroll
    for (int pp = 0; pp < 2; pp++) {
        const uint4* src = (const uint4*)&g_pidx[bc][p0 + pp][z * KZB];
        uint4* dst = (uint4*)&s_bin[pp][0];
        for (int j = tid; j < KZB / 16; j += 128) dst[j] = src[j];
    }
    __syncthreads();

    const __half* ampb = &g_ampH[bc][0][0];
    float d[2][6][4];
#pragma unroll
    for (int pp = 0; pp < 2; pp++)
#pragma unroll
        for (int i = 0; i < 6; i++)
#pragma unroll
            for (int r = 0; r < 4; r++) d[pp][i][r] = 0.f;

    int kbase = z * KZB + w * (KZB / 4);              // 96 t per warp
#pragma unroll
    for (int ks = 0; ks < (KZB / 4) / 16; ks++) {     // 6 ksteps
        int k0 = kbase + ks * 16;
        // ---- A fragments (amp), 2 m-tiles, shared across both p ----
        unsigned int a[2][4];
#pragma unroll
        for (int mt = 0; mt < 2; mt++) {
            const __half* r0 = ampb + (mt * 16 + gid) * NKEEP + k0 + 2 * tig;
            const __half* r1 = r0 + 8 * NKEEP;
            a[mt][0] = *(const unsigned int*)r0;
            a[mt][1] = *(const unsigned int*)r1;
            a[mt][2] = *(const unsigned int*)(r0 + 8);
            a[mt][3] = *(const unsigned int*)(r1 + 8);
        }
        int tl = w * (KZB / 4) + ks * 16 + 2 * tig;   // local bin index
#pragma unroll
        for (int pp = 0; pp < 2; pp++) {
            unsigned int blo = *(const unsigned short*)&s_bin[pp][tl];
            unsigned int bhi = *(const unsigned short*)&s_bin[pp][tl + 8];
            int b00 = blo & 255, b01 = (blo >> 8) & 255;
            int b10 = bhi & 255, b11 = (bhi >> 8) & 255;
#pragma unroll
            for (int nt = 0; nt < 3; nt++) {
                int n = nt * 8 + gid;
                unsigned int bb0 = ((b00 == n) ? 0x3C00u : 0u)
                                 | ((b01 == n) ? 0x3C000000u : 0u);
                unsigned int bb1 = ((b10 == n) ? 0x3C00u : 0u)
                                 | ((b11 == n) ? 0x3C000000u : 0u);
#pragma unroll
                for (int mt = 0; mt < 2; mt++) {
                    float* dd = d[pp][mt * 3 + nt];
                    asm volatile(
                        "mma.sync.aligned.m16n8k16.row.col.f32.f16.f16.f32 "
                        "{%0,%1,%2,%3},{%4,%5,%6,%7},{%8,%9},{%0,%1,%2,%3};"
                        : "+f"(dd[0]), "+f"(dd[1]), "+f"(dd[2]), "+f"(dd[3])
                        : "r"(a[mt][0]), "r"(a[mt][1]), "r"(a[mt][2]), "r"(a[mt][3]),
                          "r"(bb0), "r"(bb1));
                }
            }
        }
    }

    // ---- intra-block warp reduce per p; write z-partials (d-frag layout) ----
#pragma unroll
    for (int pp = 0; pp < 2; pp++) {
        if (w > 0) {
#pragma unroll
            for (int i = 0; i < 6; i++)
#pragma unroll
                for (int r = 0; r < 4; r++)
                    s_red[w - 1][i * 4 + r][lane] = d[pp][i][r];
        }
        __syncthreads();
        if (w == 0) {
#pragma unroll
            for (int i = 0; i < 6; i++)
#pragma unroll
                for (int r = 0; r < 4; r++) {
                    float v = d[pp][i][r] + s_red[0][i * 4 + r][lane]
                            + s_red[1][i * 4 + r][lane]
                            + s_red[2][i * 4 + r][lane];
                    g_part[bc][p0 + pp][z][i * 4 + r][lane] = v;
                }
        }
        __syncthreads();
    }

    // ---- last z-block: reduce over z + MI ----
    __threadfence();
    if (tid == 0) s_old = atomicAdd(&g_cnt[bc][px], 1);
    __syncthreads();
    if (s_old != ZS - 1) return;
    __threadfence();

    if (w < 2) {
        int p = p0 + w;
        float dd[6][4];
#pragma unroll
        for (int i = 0; i < 6; i++)
#pragma unroll
            for (int r = 0; r < 4; r++) {
                float v = 0.f;
#pragma unroll
                for (int zz = 0; zz < ZS; zz++)
                    v += g_part[bc][p][zz][i * 4 + r][lane];
                dd[i][r] = v;
            }
        // scatter D -> s_sum[w][ch][bin]
#pragma unroll
        for (int mt = 0; mt < 2; mt++)
#pragma unroll
            for (int nt = 0; nt < 3; nt++) {
                float* dr = dd[mt * 3 + nt];
                int ch0 = mt * 16 + gid;
                int cb  = nt * 8 + 2 * tig;
                s_sum[w][ch0][cb]         = dr[0];
                s_sum[w][ch0][cb + 1]     = dr[1];
                s_sum[w][ch0 + 8][cb]     = dr[2];
                s_sum[w][ch0 + 8][cb + 1] = dr[3];
            }
        __syncwarp();

        float means[NBINS];
        float tot = 0.f;
#pragma unroll
        for (int k = 0; k < NBINS; k++) {
            float cnt = s_sum[w][30][k];
            float s   = s_sum[w][lane][k];
            float m   = __fdiv_rn(s, fmaxf(cnt, 1e-9f));
            means[k]  = m;
            tot      += m;
        }
        float denom = fmaxf(tot, 1e-9f);
        float acc = 0.f;
#pragma unroll
        for (int k = 0; k < NBINS; k++) {
            float pr = __fdiv_rn(means[k], denom);
            acc += pr * logf(pr + 1e-9f);
        }
        const float LOG_NB = 2.8903717578961645f;
        if (lane < AMP_NB)
            out[(bc * PHA_NB + p) * AMP_NB + lane] = (LOG_NB + acc) / LOG_NB;
    }
}

// ---------------- launch -----------------------------------------------------
extern "C" void kernel_launch(void* const* d_in, const int* in_sizes, int n_in,
                              void* d_out, int out_size) {
    const float* x = (const float*)d_in[0];
    float* out = (float*)d_out;

    dft_kernel<<<dim3(NBC, 4), 1024>>>(x);
    prefix_kernel<<<dim3(NKEEP / 128, NBC, NCH), 128>>>();
    tail_kernel<<<dim3(NKEEP / 128, NBC, 5), 128>>>();
    mi_mma_kernel<<<dim3(PHA_NB / 2, NBC, ZS), 128>>>(out);
}